// round 6
// baseline (speedup 1.0000x reference)
#include <cuda_runtime.h>
#include <cuda_bf16.h>
#include <cstdint>

#define K_DIM 1024
#define E_DIM 64
#define NVEC  65536
#define NPIX  4194304
#define CTA_M 128
#define NTHR  256
#define CAP   16
#define MARGIN 8e-3f

// SMEM byte layout
#define ZBF_STRIDE_B 136   // 68 bf16 per z row
#define ZF_STRIDE_F  68    // 68 fp32 per z row (272B, 16B-aligned)
#define CB_OFF   0          // fragment-major bf16 codebook: 32768 uint32 = 128 KB
#define ZBF_OFF  131072
#define ZF_OFF   148480
#define E2_OFF   183296
#define BK_OFF   187392
#define CAND_OFF 187904
#define SMEM_TOTAL 220672

__device__ double d_loss_acc;
__device__ float  d_e2[K_DIM];
// Fragment-major bf16 codebook: word = ((k>>3)*4 + ks)*64 + ((k&7)*4+q)*2 + w
// so thread lane l=(g*4+q) reads its (b0,b1) pair as ONE uint2 at index l.
__device__ uint32_t d_cbfrag[K_DIM * E_DIM / 2];

// ---- packed f32x2 helpers (exact re-rank, proven in round 3) ----
__device__ __forceinline__ void fma2(unsigned long long& d,
                                     unsigned long long a, unsigned long long b) {
    asm("fma.rn.f32x2 %0, %1, %2, %0;" : "+l"(d) : "l"(a), "l"(b));
}
__device__ __forceinline__ void add2(unsigned long long& d, unsigned long long a) {
    asm("add.rn.f32x2 %0, %0, %1;" : "+l"(d) : "l"(a));
}
__device__ __forceinline__ float2 unpack2(unsigned long long v) {
    float2 r; asm("mov.b64 {%0, %1}, %2;" : "=f"(r.x), "=f"(r.y) : "l"(v)); return r;
}

// Baseline sm_80 tensor-core MMA (valid on compute_103, runs on Blackwell HMMA).
// D: d0=(g,2q) d1=(g,2q+1) d2=(g+8,2q) d3=(g+8,2q+1); g=lane/4, q=lane%4.
__device__ __forceinline__ void mma_bf16(float& d0, float& d1, float& d2, float& d3,
    uint32_t a0, uint32_t a1, uint32_t a2, uint32_t a3, uint32_t b0, uint32_t b1) {
    asm volatile("mma.sync.aligned.m16n8k16.row.col.f32.bf16.bf16.f32 "
        "{%0,%1,%2,%3}, {%4,%5,%6,%7}, {%8,%9}, {%0,%1,%2,%3};"
        : "+f"(d0), "+f"(d1), "+f"(d2), "+f"(d3)
        : "r"(a0), "r"(a1), "r"(a2), "r"(a3), "r"(b0), "r"(b1));
}

__global__ void init_kernel() { d_loss_acc = 0.0; }

__global__ void e2_kernel(const float* __restrict__ cb) {
    int k = blockIdx.x * blockDim.x + threadIdx.x;
    if (k < K_DIM) {
        const float4* r = reinterpret_cast<const float4*>(cb + k * E_DIM);
        float s = 0.f;
#pragma unroll
        for (int i = 0; i < E_DIM / 4; i++) {
            float4 v = r[i];
            s += v.x * v.x + v.y * v.y + v.z * v.z + v.w * v.w;
        }
        d_e2[k] = s;
    }
}

// Build fragment-major bf16 codebook. Thread handles one element pair (k, 2cp..2cp+1).
__global__ void cbconv_kernel(const float* __restrict__ cb) {
    int idx = blockIdx.x * 256 + threadIdx.x;     // idx in [0, K_DIM*32)
    if (idx < K_DIM * 32) {
        int k  = idx >> 5;
        int cp = idx & 31;                        // element pair index
        float2 v = reinterpret_cast<const float2*>(cb)[idx];
        __nv_bfloat162 h = __float22bfloat162_rn(v);
        int W = ((k >> 3) * 4 + (cp >> 3)) * 64   // (nt*4 + ks)*64
              + ((k & 7) * 4 + (cp & 3)) * 2      // lane-slot*2
              + ((cp >> 2) & 1);                  // b0 / b1
        d_cbfrag[W] = *reinterpret_cast<uint32_t*>(&h);
    }
}

// Candidate push: prune when full; if still full, evict the max-da entry
// (never silently drop a closer candidate).
__device__ __forceinline__ void push_cand(uint2* cand, int& cnt,
                                          float bestA0, float bestA1,
                                          float da, int key) {
    if (cnt == CAP) {
        int w = 0;
#pragma unroll 1
        for (int i = 0; i < CAP; i++) {
            uint2 e = cand[i];
            float lim = (e.y & 1) ? bestA1 : bestA0;
            if (__uint_as_float(e.x) < lim + MARGIN) cand[w++] = e;
        }
        cnt = w;
        if (cnt == CAP) {                          // evict max-da if new is closer
            int mi = 0; float mv = __uint_as_float(cand[0].x);
#pragma unroll 1
            for (int i = 1; i < CAP; i++) {
                float v = __uint_as_float(cand[i].x);
                if (v > mv) { mv = v; mi = i; }
            }
            if (da < mv) cand[mi] = make_uint2(__float_as_uint(da), (uint32_t)key);
            return;
        }
    }
    cand[cnt++] = make_uint2(__float_as_uint(da), (uint32_t)key);
}

__global__ __launch_bounds__(NTHR, 1)
void vq_mma_kernel(const float* __restrict__ z,
                   const float* __restrict__ cb,
                   float* __restrict__ out_vq) {
    extern __shared__ char sm[];
    float* s_e2 = reinterpret_cast<float*>(sm + E2_OFF);
    int*   s_bk = reinterpret_cast<int*>(sm + BK_OFF);

    const int tid = threadIdx.x, lane = tid & 31, wid = tid >> 5;
    const int g = lane >> 2, q = lane & 3;
    const int m0 = blockIdx.x * CTA_M;
    const int base_cta = (m0 >> 12) * (E_DIM * 4096) + (m0 & 4095);

    // ---- prologue: fragment codebook (flat memcpy), e2, z tile (fp32 + bf16) ----
    {
        const uint4* src = reinterpret_cast<const uint4*>(d_cbfrag);
        uint4* dst = reinterpret_cast<uint4*>(sm + CB_OFF);
        for (int i = tid; i < K_DIM * E_DIM * 2 / 16; i += NTHR) dst[i] = src[i];
    }
    for (int i = tid; i < K_DIM; i += NTHR) s_e2[i] = d_e2[i];
    {
        float* s_zf = reinterpret_cast<float*>(sm + ZF_OFF);
        for (int idx = tid; idx < CTA_M * 32; idx += NTHR) {
            int i = idx & 127, cp = idx >> 7;
            float v0 = z[base_cta + (2 * cp)     * 4096 + i];
            float v1 = z[base_cta + (2 * cp + 1) * 4096 + i];
            s_zf[i * ZF_STRIDE_F + 2 * cp]     = v0;
            s_zf[i * ZF_STRIDE_F + 2 * cp + 1] = v1;
            __nv_bfloat162 h = __float22bfloat162_rn(make_float2(v0, v1));
            *reinterpret_cast<uint32_t*>(sm + ZBF_OFF + i * ZBF_STRIDE_B + cp * 4) =
                *reinterpret_cast<uint32_t*>(&h);
        }
    }
    __syncthreads();

    // ---- A fragments (z rows r0, r0+8), kept in regs for whole k-loop ----
    const int r0 = wid * 16 + g;
    uint32_t A0[4], A1[4], A2[4], A3[4];
#pragma unroll
    for (int ks = 0; ks < 4; ks++) {
        const char* za = sm + ZBF_OFF + ks * 32 + q * 4;
        A0[ks] = *reinterpret_cast<const uint32_t*>(za + r0 * ZBF_STRIDE_B);
        A1[ks] = *reinterpret_cast<const uint32_t*>(za + (r0 + 8) * ZBF_STRIDE_B);
        A2[ks] = *reinterpret_cast<const uint32_t*>(za + r0 * ZBF_STRIDE_B + 16);
        A3[ks] = *reinterpret_cast<const uint32_t*>(za + (r0 + 8) * ZBF_STRIDE_B + 16);
    }

    float bestA0 = 3.4e38f, bestA1 = 3.4e38f;
    int cnt = 0;
    uint2* cand = reinterpret_cast<uint2*>(sm + CAND_OFF) + tid * CAP;
    const uint2* cbf = reinterpret_cast<const uint2*>(sm + CB_OFF);
    const float2* e2p = reinterpret_cast<const float2*>(s_e2);

    // ---- main loop: 128 tiles of 8 codes ----
#pragma unroll 1
    for (int nt = 0; nt < K_DIM / 8; nt++) {
        float d0 = 0.f, d1 = 0.f, d2 = 0.f, d3 = 0.f;
#pragma unroll
        for (int ks = 0; ks < 4; ks++) {
            uint2 b = cbf[(nt * 4 + ks) * 32 + lane];   // one LDS.64, conflict-free
            mma_bf16(d0, d1, d2, d3, A0[ks], A1[ks], A2[ks], A3[ks], b.x, b.y);
        }
        const int k0 = nt * 8 + 2 * q;
        float2 e2v = e2p[nt * 4 + q];                    // e2[k0], e2[k0+1]
        float da00 = fmaf(-2.f, d0, e2v.x);   // row r0,   code k0
        float da01 = fmaf(-2.f, d1, e2v.y);   // row r0,   code k0+1
        float da10 = fmaf(-2.f, d2, e2v.x);   // row r0+8, code k0
        float da11 = fmaf(-2.f, d3, e2v.y);   // row r0+8, code k0+1
        bool f00 = da00 < bestA0 + MARGIN;
        bool f01 = da01 < bestA0 + MARGIN;
        bool f10 = da10 < bestA1 + MARGIN;
        bool f11 = da11 < bestA1 + MARGIN;
        bestA0 = fminf(bestA0, fminf(da00, da01));
        bestA1 = fminf(bestA1, fminf(da10, da11));
        if (f00 | f01 | f10 | f11) {          // rare; ascending k within each row
            if (f00) push_cand(cand, cnt, bestA0, bestA1, da00, (k0 << 1));
            if (f01) push_cand(cand, cnt, bestA0, bestA1, da01, ((k0 + 1) << 1));
            if (f10) push_cand(cand, cnt, bestA0, bestA1, da10, (k0 << 1) | 1);
            if (f11) push_cand(cand, cnt, bestA0, bestA1, da11, ((k0 + 1) << 1) | 1);
        }
    }

    // ---- exact fp32 re-rank (round-3 arithmetic, bit-identical structure) ----
    const float* zrow0 = reinterpret_cast<const float*>(sm + ZF_OFF) + r0 * ZF_STRIDE_F;
    const float* zrow1 = zrow0 + 8 * ZF_STRIDE_F;
    float z2_0 = 0.f, z2_1 = 0.f;
#pragma unroll
    for (int i = 0; i < 32; i++) {
        float2 v0 = reinterpret_cast<const float2*>(zrow0)[i];
        float2 v1 = reinterpret_cast<const float2*>(zrow1)[i];
        z2_0 = __fadd_rn(z2_0, __fadd_rn(__fmul_rn(v0.x, v0.x), __fmul_rn(v0.y, v0.y)));
        z2_1 = __fadd_rn(z2_1, __fadd_rn(__fmul_rn(v1.x, v1.x), __fmul_rn(v1.y, v1.y)));
    }

    float bE0 = 3.4e38f, bE1 = 3.4e38f;
    int   bK0 = 0,       bK1 = 0;
#pragma unroll 1
    for (int i = 0; i < cnt; i++) {
        uint2 e = cand[i];
        int k = (int)(e.y >> 1), row = (int)(e.y & 1);
        const ulonglong2* zp = reinterpret_cast<const ulonglong2*>(row ? zrow1 : zrow0);
        const ulonglong2* ep = reinterpret_cast<const ulonglong2*>(cb + k * E_DIM);
        unsigned long long a0 = 0ull, a1 = 0ull, a2 = 0ull, a3 = 0ull;
#pragma unroll
        for (int t = 0; t < 8; t++) {
            ulonglong2 zz0 = zp[2 * t], zz1 = zp[2 * t + 1];
            ulonglong2 ee0 = ep[2 * t], ee1 = ep[2 * t + 1];
            fma2(a0, zz0.x, ee0.x);
            fma2(a1, zz0.y, ee0.y);
            fma2(a2, zz1.x, ee1.x);
            fma2(a3, zz1.y, ee1.y);
        }
        add2(a0, a1); add2(a2, a3); add2(a0, a2);
        float2 s = unpack2(a0);
        float dot = __fadd_rn(s.x, s.y);
        float zz2 = row ? z2_1 : z2_0;
        float de  = __fmaf_rn(-2.f, dot, __fadd_rn(zz2, s_e2[k]));  // == t - 2*dot
        // strict < with ties to LOWEST k (candidates may not be fully sorted
        // after evict-max, so make the tie-break explicit)
        if (row) { if (de < bE1 || (de == bE1 && k < bK1)) { bE1 = de; bK1 = k; } }
        else     { if (de < bE0 || (de == bE0 && k < bK0)) { bE0 = de; bK0 = k; } }
    }

    // ---- merge across quad (lexicographic: dist, then lowest k) ----
#pragma unroll
    for (int o = 1; o < 4; o <<= 1) {
        float oe0 = __shfl_xor_sync(0xFFFFFFFFu, bE0, o);
        int   ok0 = __shfl_xor_sync(0xFFFFFFFFu, bK0, o);
        if (oe0 < bE0 || (oe0 == bE0 && ok0 < bK0)) { bE0 = oe0; bK0 = ok0; }
        float oe1 = __shfl_xor_sync(0xFFFFFFFFu, bE1, o);
        int   ok1 = __shfl_xor_sync(0xFFFFFFFFu, bK1, o);
        if (oe1 < bE1 || (oe1 == bE1 && ok1 < bK1)) { bE1 = oe1; bK1 = ok1; }
    }
    if (q == 0) { s_bk[r0] = bK0; s_bk[r0 + 8] = bK1; }
    __syncthreads();

    // ---- coalesced epilogue: threads 0..127 each own one row ----
    if (tid < CTA_M) {
        int k = s_bk[tid];
        const float4* er = reinterpret_cast<const float4*>(cb + k * E_DIM);
        float local = 0.f;
#pragma unroll
        for (int c4 = 0; c4 < 16; c4++) {
            float4 e = __ldg(&er[c4]);
            int a = base_cta + (4 * c4) * 4096 + tid;
            float p0 = z[a], p1 = z[a + 4096], p2 = z[a + 8192], p3 = z[a + 12288];
            float q0 = e.x - p0, q1 = e.y - p1, q2 = e.z - p2, q3 = e.w - p3;
            local += q0 * q0 + q1 * q1 + q2 * q2 + q3 * q3;
            out_vq[a]         = e.x;
            out_vq[a + 4096]  = e.y;
            out_vq[a + 8192]  = e.z;
            out_vq[a + 12288] = e.w;
        }
#pragma unroll
        for (int o = 16; o; o >>= 1)
            local += __shfl_xor_sync(0xFFFFFFFFu, local, o);
        if (lane == 0) atomicAdd(&d_loss_acc, (double)local);
    }
}

__global__ void fin_kernel(float* out, int has_loss) {
    if (has_loss)
        out[0] = (float)(1.25 * d_loss_acc / (double)NPIX);
}

extern "C" void kernel_launch(void* const* d_in, const int* in_sizes, int n_in,
                              void* d_out, int out_size) {
    const float* z  = (const float*)d_in[0];
    const float* cb = (const float*)d_in[1];
    if (n_in >= 2 && in_sizes[0] == K_DIM * E_DIM && in_sizes[1] == NPIX) {
        const float* t = z; z = cb; cb = t;   // defensive: inputs swapped
    }

    float* out = (float*)d_out;
    int voff = out_size - NPIX;
    if (voff < 0) voff = 0;
    float* out_vq = out + voff;

    cudaFuncSetAttribute(vq_mma_kernel,
                         cudaFuncAttributeMaxDynamicSharedMemorySize, SMEM_TOTAL);

    init_kernel<<<1, 1>>>();
    e2_kernel<<<K_DIM / 256, 256>>>(cb);
    cbconv_kernel<<<K_DIM * 32 / 256, 256>>>(cb);
    vq_mma_kernel<<<NVEC / CTA_M, NTHR, SMEM_TOTAL>>>(z, cb, out_vq);
    fin_kernel<<<1, 1>>>(out, voff > 0 ? 1 : 0);
}

// round 7
// speedup vs baseline: 8.4956x; 8.4956x over previous
#include <cuda_runtime.h>
#include <cuda_bf16.h>

#define K_DIM 1024
#define E_DIM 64
#define NVEC  (16 * 64 * 64)        // 65536 vectors
#define NPIX  (16 * 64 * 64 * 64)   // 4194304 output elements (vq part)
#define KC    128                   // codebook entries per shared-memory chunk

__device__ double d_loss_acc;
__device__ float  d_e2[K_DIM];

// ---- packed f32x2 helpers (sm_103a) ----
__device__ __forceinline__ void fma2(unsigned long long& d,
                                     unsigned long long a,
                                     unsigned long long b) {
    asm("fma.rn.f32x2 %0, %1, %2, %0;" : "+l"(d) : "l"(a), "l"(b));
}
__device__ __forceinline__ void add2(unsigned long long& d,
                                     unsigned long long a) {
    asm("add.rn.f32x2 %0, %0, %1;" : "+l"(d) : "l"(a));
}
__device__ __forceinline__ float2 unpack2(unsigned long long v) {
    float2 r;
    asm("mov.b64 {%0, %1}, %2;" : "=f"(r.x), "=f"(r.y) : "l"(v));
    return r;
}
__device__ __forceinline__ unsigned long long pack2(float lo, float hi) {
    unsigned long long v;
    asm("mov.b64 %0, {%1, %2};" : "=l"(v) : "f"(lo), "f"(hi));
    return v;
}

// ||e_k||^2 for every codebook row; also zeroes the loss accumulator.
__global__ void e2_kernel(const float* __restrict__ cb) {
    if (blockIdx.x == 0 && threadIdx.x == 0) d_loss_acc = 0.0;
    int k = blockIdx.x * blockDim.x + threadIdx.x;
    if (k < K_DIM) {
        const float4* r = reinterpret_cast<const float4*>(cb + k * E_DIM);
        float s = 0.f;
#pragma unroll
        for (int i = 0; i < E_DIM / 4; i++) {
            float4 v = r[i];
            s += v.x * v.x + v.y * v.y + v.z * v.z + v.w * v.w;
        }
        d_e2[k] = s;
    }
}

// T=2 z-vectors per thread, j-loop unrolled by 2 codes:
// 16 independent FFMA2 chains per iteration keep the fma pipe fed while the
// broadcast LDS batches (uniform address, N=1) for the other row are in flight.
__global__ __launch_bounds__(128, 2)
void vq_kernel(const float* __restrict__ z,
               const float* __restrict__ cb,
               float* __restrict__ out_vq) {
    __shared__ float sh_cb[KC * E_DIM];   // 32 KB
    __shared__ float sh_e2[KC];

    const int tid = threadIdx.x;
    const int n0  = blockIdx.x * 256 + tid;     // vector ids n0 and n0+128
    const int n1  = n0 + 128;
    const int base0 = (n0 >> 12) * (E_DIM * 4096) + (n0 & 4095);
    const int base1 = (n1 >> 12) * (E_DIM * 4096) + (n1 & 4095);

    // Both z rows in registers as packed f32x2.
    unsigned long long zr0[E_DIM / 2], zr1[E_DIM / 2];
#pragma unroll
    for (int i = 0; i < E_DIM / 2; i++) {
        zr0[i] = pack2(z[base0 + (2 * i) * 4096], z[base0 + (2 * i + 1) * 4096]);
        zr1[i] = pack2(z[base1 + (2 * i) * 4096], z[base1 + (2 * i + 1) * 4096]);
    }

    // ||z||^2 fp32, sequential pair order (reference-matching rounding anchor).
    float z20 = 0.f, z21 = 0.f;
#pragma unroll
    for (int i = 0; i < E_DIM / 2; i++) {
        float2 v0 = unpack2(zr0[i]);
        float2 v1 = unpack2(zr1[i]);
        z20 = __fadd_rn(z20, __fadd_rn(__fmul_rn(v0.x, v0.x), __fmul_rn(v0.y, v0.y)));
        z21 = __fadd_rn(z21, __fadd_rn(__fmul_rn(v1.x, v1.x), __fmul_rn(v1.y, v1.y)));
    }

    float best0 = 3.4e38f, best1 = 3.4e38f;
    int   bidx0 = 0,       bidx1 = 0;

    for (int k0 = 0; k0 < K_DIM; k0 += KC) {
        __syncthreads();
        // Cooperative chunk load: KC*64 floats = 2048 float4 / 128 threads
        const float4* src = reinterpret_cast<const float4*>(cb + k0 * E_DIM);
        float4* dst = reinterpret_cast<float4*>(sh_cb);
#pragma unroll
        for (int i = 0; i < (KC * E_DIM / 4) / 128; i++)
            dst[tid + i * 128] = src[tid + i * 128];
        sh_e2[tid] = d_e2[k0 + tid];              // KC == blockDim
        __syncthreads();

#pragma unroll 1
        for (int j = 0; j < KC; j += 2) {
            const ulonglong2* eA =
                reinterpret_cast<const ulonglong2*>(sh_cb + j * E_DIM);
            const ulonglong2* eB =
                reinterpret_cast<const ulonglong2*>(sh_cb + (j + 1) * E_DIM);
            // 16 independent accumulator chains (2 vec x 2 codes x 4 chains)
            unsigned long long a0 = 0, a1 = 0, a2 = 0, a3 = 0;   // vec0 x code j
            unsigned long long b0 = 0, b1 = 0, b2 = 0, b3 = 0;   // vec1 x code j
            unsigned long long c0 = 0, c1 = 0, c2 = 0, c3 = 0;   // vec0 x code j+1
            unsigned long long d0 = 0, d1 = 0, d2 = 0, d3 = 0;   // vec1 x code j+1
#pragma unroll
            for (int i = 0; i < 8; i++) {          // 4 LDS.128 + 16 FFMA2 per step
                ulonglong2 xA0 = eA[2 * i];
                ulonglong2 xA1 = eA[2 * i + 1];
                ulonglong2 xB0 = eB[2 * i];
                ulonglong2 xB1 = eB[2 * i + 1];
                fma2(a0, zr0[4 * i + 0], xA0.x);
                fma2(b0, zr1[4 * i + 0], xA0.x);
                fma2(c0, zr0[4 * i + 0], xB0.x);
                fma2(d0, zr1[4 * i + 0], xB0.x);
                fma2(a1, zr0[4 * i + 1], xA0.y);
                fma2(b1, zr1[4 * i + 1], xA0.y);
                fma2(c1, zr0[4 * i + 1], xB0.y);
                fma2(d1, zr1[4 * i + 1], xB0.y);
                fma2(a2, zr0[4 * i + 2], xA1.x);
                fma2(b2, zr1[4 * i + 2], xA1.x);
                fma2(c2, zr0[4 * i + 2], xB1.x);
                fma2(d2, zr1[4 * i + 2], xB1.x);
                fma2(a3, zr0[4 * i + 3], xA1.y);
                fma2(b3, zr1[4 * i + 3], xA1.y);
                fma2(c3, zr0[4 * i + 3], xB1.y);
                fma2(d3, zr1[4 * i + 3], xB1.y);
            }
            // Per-(vec,code) reduction: identical tree to the round-3 kernel.
            add2(a0, a1); add2(a2, a3); add2(a0, a2);
            add2(b0, b1); add2(b2, b3); add2(b0, b2);
            add2(c0, c1); add2(c2, c3); add2(c0, c2);
            add2(d0, d1); add2(d2, d3); add2(d0, d2);
            float2 sA0 = unpack2(a0), sA1 = unpack2(b0);
            float2 sB0 = unpack2(c0), sB1 = unpack2(d0);
            float dotA0 = __fadd_rn(sA0.x, sA0.y);
            float dotA1 = __fadd_rn(sA1.x, sA1.y);
            float dotB0 = __fadd_rn(sB0.x, sB0.y);
            float dotB1 = __fadd_rn(sB1.x, sB1.y);
            float e2A = sh_e2[j], e2B = sh_e2[j + 1];
            // Reference fp32 rounding: (z2 + e2) - 2*dot (fma form, exact 2*dot).
            // Code j strictly before j+1: first-occurrence tie-break preserved.
            float dA0 = __fmaf_rn(-2.0f, dotA0, __fadd_rn(z20, e2A));
            float dA1 = __fmaf_rn(-2.0f, dotA1, __fadd_rn(z21, e2A));
            if (dA0 < best0) { best0 = dA0; bidx0 = k0 + j; }
            if (dA1 < best1) { best1 = dA1; bidx1 = k0 + j; }
            float dB0 = __fmaf_rn(-2.0f, dotB0, __fadd_rn(z20, e2B));
            float dB1 = __fmaf_rn(-2.0f, dotB1, __fadd_rn(z21, e2B));
            if (dB0 < best0) { best0 = dB0; bidx0 = k0 + j + 1; }
            if (dB1 < best1) { best1 = dB1; bidx1 = k0 + j + 1; }
        }
    }

    // Epilogue: gather winning rows (L2-resident), write vq, accumulate loss.
    float local = 0.f;
    {
        const float2* er = reinterpret_cast<const float2*>(cb + bidx0 * E_DIM);
#pragma unroll
        for (int i = 0; i < E_DIM / 2; i++) {
            float2 e  = __ldg(&er[i]);
            float2 zp = unpack2(zr0[i]);
            float q0 = e.x - zp.x, q1 = e.y - zp.y;
            local += q0 * q0 + q1 * q1;
            out_vq[base0 + (2 * i)     * 4096] = e.x;
            out_vq[base0 + (2 * i + 1) * 4096] = e.y;
        }
    }
    {
        const float2* er = reinterpret_cast<const float2*>(cb + bidx1 * E_DIM);
#pragma unroll
        for (int i = 0; i < E_DIM / 2; i++) {
            float2 e  = __ldg(&er[i]);
            float2 zp = unpack2(zr1[i]);
            float q0 = e.x - zp.x, q1 = e.y - zp.y;
            local += q0 * q0 + q1 * q1;
            out_vq[base1 + (2 * i)     * 4096] = e.x;
            out_vq[base1 + (2 * i + 1) * 4096] = e.y;
        }
    }

    // warp reduce + one double atomic per warp
#pragma unroll
    for (int o = 16; o; o >>= 1)
        local += __shfl_xor_sync(0xFFFFFFFFu, local, o);
    if ((tid & 31) == 0)
        atomicAdd(&d_loss_acc, (double)local);
}

__global__ void fin_kernel(float* out, int has_loss) {
    if (has_loss)
        out[0] = (float)(1.25 * d_loss_acc / (double)NPIX);
}

extern "C" void kernel_launch(void* const* d_in, const int* in_sizes, int n_in,
                              void* d_out, int out_size) {
    // metadata order: z [16,64,64,64] fp32, codebook [1024,64] fp32.
    const float* z  = (const float*)d_in[0];
    const float* cb = (const float*)d_in[1];
    if (n_in >= 2 && in_sizes[0] == K_DIM * E_DIM && in_sizes[1] == NPIX) {
        const float* t = z; z = cb; cb = t;   // defensive: inputs swapped
    }

    float* out = (float*)d_out;
    int voff = out_size - NPIX;            // 1 if scalar loss precedes vq_out
    if (voff < 0) voff = 0;
    float* out_vq = out + voff;

    e2_kernel<<<K_DIM / 256, 256>>>(cb);             // also zeroes loss acc
    vq_kernel<<<NVEC / 256, 128>>>(z, cb, out_vq);   // 2 vectors per thread
    fin_kernel<<<1, 1>>>(out, voff > 0 ? 1 : 0);
}